// round 17
// baseline (speedup 1.0000x reference)
#include <cuda_runtime.h>

#define BB 32
#define NN 2048
#define EPSF 5e-4f
#define HH 5.0f
#define MC 20            /* Chebyshev-Gauss nodes; degree 19 */
#define FCH 128          /* finisher pair-chunk size */
#define HCH 640          /* helper pair-chunk size (128 + 3*640 = 2048) */

typedef unsigned long long u64;

#define FMA2(d,a,b,c) asm("fma.rn.f32x2 %0,%1,%2,%3;" : "=l"(d) : "l"(a),"l"(b),"l"(c))
#define SUB2(d,a,b)   asm("sub.rn.f32x2 %0,%1,%2;"    : "=l"(d) : "l"(a),"l"(b))
#define PK2(d,lo,hi)  asm("mov.b64 %0,{%1,%2};" : "=l"(d) : "r"(__float_as_uint(lo)), "r"(__float_as_uint(hi)))
#define UPK2(lo,hi,s) do { unsigned _a,_b; asm("mov.b64 {%0,%1},%2;" : "=r"(_a),"=r"(_b) : "l"(s)); lo=__uint_as_float(_a); hi=__uint_as_float(_b); } while(0)

__device__ float g_Fp[BB*3*32];   // node partials from helper blocks 1..3
__device__ int   g_rowCtr[BB];    // zero-init; finisher resets
__device__ u64   g_acc;           // zero-init; packed (sum<<10 | count), self-resetting

// Grid (4, BB) x 512 = 128 blocks, single wave.
//  blk 1..3: pair partials for 640 scores: paired sigmoid at node W=e^{x_k}:
//            sig(a)+sig(b) = (2ab+pW)/(ab+pW+W^2). Write, fence, arrive.
//  blk 0   : finisher + pair worker for chunk [0,128). Overlapped with
//            helpers: preload all scores/labels (rank table 1/log2(n+2)
//            computed in the DRAM-latency shadow), tiny pair chunk,
//            histogram -> rank-based maxDCG -> inv. Spin on row counter,
//            fold partials, warp-parallel DCT-II, packed-f32x2 Clenshaw
//            (4 pts/thread), row sum; one packed fixed-point u64 atomic
//            accumulates the mean deterministically and detects the last row.
__global__ __launch_bounds__(512, 2)
void fused(const float* __restrict__ yp, const float* __restrict__ yt,
           float* __restrict__ out) {
    int blk = blockIdx.x, b = blockIdx.y;
    int t = threadIdx.x, w = t >> 5, lane = t & 31;

    __shared__ float2 sP[HCH/2];
    __shared__ float sF[16*33];
    __shared__ float sFn[32];
    __shared__ float2 sC2[MC];        // coefs duplicated (lo==hi) for f32x2
    __shared__ float sRed[16];
    __shared__ unsigned long long sH[16];
    __shared__ int sOff[4];
    __shared__ float sInv;

    // node for this lane: x_k = HH*cos(pi(2k+1)/(2*MC)); lanes>=MC junk,
    // masked out at the DCT (Fk=0 there).
    float W  = __expf(HH * cospif((float)(2*lane + 1) * (1.0f/(2*MC))));
    float W2 = W * W;

    if (blk != 0) {
        // ------------- helper pair blocks: 640 scores each -------------
        const float* base = yp + b*NN + FCH + (blk - 1)*HCH;
        if (t < HCH/2) {
            float2 sc = ((const float2*)base)[t];
            float ea = __expf(sc.x), eb = __expf(sc.y);
            sP[t] = make_float2(ea + eb, 2.f*ea*eb);
        }
        __syncthreads();
        const float4* P4 = (const float4*)sP + w*10;   // 10 float4 = 20 pairs
        float acc = 0.f;
        #pragma unroll
        for (int i = 0; i < 10; i++) {
            float4 q = P4[i];
            acc = fmaf(fmaf(q.x, W, q.y),
                       __frcp_rn(fmaf(q.x, W, fmaf(0.5f, q.y, W2))), acc);
            acc = fmaf(fmaf(q.z, W, q.w),
                       __frcp_rn(fmaf(q.z, W, fmaf(0.5f, q.w, W2))), acc);
        }
        sF[w*33 + lane] = acc;
        __syncthreads();
        if (w == 0) {
            float F = 0.f;
            #pragma unroll
            for (int i = 0; i < 16; i++) F += sF[i*33 + lane];
            g_Fp[(b*3 + (blk - 1))*32 + lane] = F;
        }
        __syncthreads();
        if (t == 0) {
            __threadfence();
            atomicAdd(&g_rowCtr[b], 1);
        }
        return;
    }

    // ---------------- finisher block (also chunk [0,128)) ----------------
    float4 s4 = ((const float4*)(yp + b*NN))[t];    // all 2048 scores
    float4 l4 = ((const float4*)(yt + b*NN))[t];    // all 2048 labels

    // rank table: pure function of t -> MUFU work hidden under DRAM latency
    float il[4];
    #pragma unroll
    for (int i = 0; i < 4; i++)
        il[i] = __fdividef(1.f, __log2f((float)(t + i*512 + 2)));

    int vv[4] = {(int)l4.x, (int)l4.y, (int)l4.z, (int)l4.w};

    // tiny pair chunk from registers (threads 0..31 own scores [0,128))
    if (t < 32) {
        float e0 = __expf(s4.x), e1 = __expf(s4.y);
        float e2 = __expf(s4.z), e3 = __expf(s4.w);
        sP[2*t]     = make_float2(e0 + e1, 2.f*e0*e1);
        sP[2*t + 1] = make_float2(e2 + e3, 2.f*e2*e3);
    }

    // packed label histogram (registers only)
    unsigned long long pk = (1ULL << (12*vv[0])) + (1ULL << (12*vv[1]))
                          + (1ULL << (12*vv[2])) + (1ULL << (12*vv[3]));
    #pragma unroll
    for (int o = 16; o; o >>= 1) pk += __shfl_xor_sync(0xffffffffu, pk, o);
    if (lane == 0) sH[w] = pk;
    __syncthreads();

    // pair loop over 64 pairs: 2 float4 per warp
    const float4* P4 = (const float4*)sP + w*2;
    float acc = 0.f;
    #pragma unroll
    for (int i = 0; i < 2; i++) {
        float4 q = P4[i];
        acc = fmaf(fmaf(q.x, W, q.y),
                   __frcp_rn(fmaf(q.x, W, fmaf(0.5f, q.y, W2))), acc);
        acc = fmaf(fmaf(q.z, W, q.w),
                   __frcp_rn(fmaf(q.z, W, fmaf(0.5f, q.w, W2))), acc);
    }
    sF[w*33 + lane] = acc;
    __syncthreads();

    if (w == 0) {            // fold own pair partials -> sFn
        float F = 0.f;
        #pragma unroll
        for (int i = 0; i < 16; i++) F += sF[i*33 + lane];
        sFn[lane] = F;
    } else if (w == 1) {     // fold histogram -> rank boundaries
        unsigned long long hh = (lane < 16) ? sH[lane] : 0ULL;
        #pragma unroll
        for (int o = 8; o; o >>= 1) hh += __shfl_xor_sync(0xffffffffu, hh, o);
        if (lane == 0) {
            int c4 = (int)((hh >> 48) & 0xFFF);
            int c3 = (int)((hh >> 36) & 0xFFF);
            int c2 = (int)((hh >> 24) & 0xFFF);
            int c1 = (int)((hh >> 12) & 0xFFF);
            sOff[0] = c4;  sOff[1] = c4 + c3;
            sOff[2] = c4 + c3 + c2;  sOff[3] = c4 + c3 + c2 + c1;
        }
    }
    __syncthreads();

    // rank-based maxDCG: gains from boundaries, rank weights precomputed
    int B4 = sOff[0], B3 = sOff[1], B2 = sOff[2], B1 = sOff[3];
    float mdcg = 0.f;
    #pragma unroll
    for (int i = 0; i < 4; i++) {
        int n = t + i*512;
        int vr = 4 - (n >= B4) - (n >= B3) - (n >= B2) - (n >= B1);
        mdcg = fmaf((float)((1 << vr) - 1), il[i], mdcg);
    }
    #pragma unroll
    for (int o = 16; o; o >>= 1) mdcg += __shfl_xor_sync(0xffffffffu, mdcg, o);
    if (lane == 0) sRed[w] = mdcg;
    __syncthreads();
    if (t == 0) {
        float x = 0.f;
        #pragma unroll
        for (int i = 0; i < 16; i++) x += sRed[i];
        sInv = 1.0f / fmaxf(x, EPSF);
        // wait for this row's 3 helper blocks (all 128 blocks co-resident)
        while (*(volatile int*)&g_rowCtr[b] != 3) __nanosleep(32);
        g_rowCtr[b] = 0;                          // reset for next graph replay
    }
    __syncthreads();
    __threadfence();                              // acquire helper partials

    // fold helper partials into sFn
    if (t < 96) sF[t] = g_Fp[b*96 + t];
    __syncthreads();
    if (t < 32) {
        float F = sFn[t];
        #pragma unroll
        for (int i = 0; i < 3; i++) F += sF[i*32 + t];
        sFn[t] = F;
    }
    __syncthreads();

    // warp-parallel DCT-II: c_m = (2/MC) sum_k F_k cos(pi m(2k+1)/(2MC));
    // lanes >= MC masked; coefs duplicated into float2 for packed Clenshaw.
    float Fk = (lane < MC) ? sFn[lane] : 0.f;
    if (w < 10) {
        #pragma unroll
        for (int j = 0; j < 2; j++) {
            int m = w + 10*j;
            float term = Fk * cospif((float)(m*(2*lane + 1)) * (1.0f/(2*MC)));
            #pragma unroll
            for (int o = 16; o; o >>= 1) term += __shfl_xor_sync(0xffffffffu, term, o);
            if (lane == 0) {
                float cc = term * (2.0f/MC);
                if (m == 0) cc *= 0.5f;
                sC2[m] = make_float2(cc, cc);
            }
        }
    }
    __syncthreads();

    // packed-f32x2 Clenshaw at 4 points/thread (2 packs)
    float u0 = fminf(fmaxf(s4.x * (1.0f/HH), -1.f), 1.f);
    float u1 = fminf(fmaxf(s4.y * (1.0f/HH), -1.f), 1.f);
    float u2 = fminf(fmaxf(s4.z * (1.0f/HH), -1.f), 1.f);
    float u3 = fminf(fmaxf(s4.w * (1.0f/HH), -1.f), 1.f);
    u64 u01, u23, tu01, tu23;
    PK2(u01,  u0,      u1);
    PK2(u23,  u2,      u3);
    PK2(tu01, u0 + u0, u1 + u1);
    PK2(tu23, u2 + u2, u3 + u3);
    u64 y1a = 0ULL, y2a = 0ULL, y1b = 0ULL, y2b = 0ULL;
    #pragma unroll
    for (int m = MC - 1; m >= 1; m--) {
        u64 cd = *reinterpret_cast<const u64*>(&sC2[m]);
        u64 ta, tb;
        FMA2(ta, tu01, y1a, cd); SUB2(ta, ta, y2a); y2a = y1a; y1a = ta;
        FMA2(tb, tu23, y1b, cd); SUB2(tb, tb, y2b); y2b = y1b; y1b = tb;
    }
    u64 cd0 = *reinterpret_cast<const u64*>(&sC2[0]);
    u64 Fa, Fb;
    FMA2(Fa, u01, y1a, cd0); SUB2(Fa, Fa, y2a);
    FMA2(Fb, u23, y1b, cd0); SUB2(Fb, Fb, y2b);
    float F0, F1, F2, F3;
    UPK2(F0, F1, Fa);
    UPK2(F2, F3, Fb);

    float FF[4] = {F0, F1, F2, F3};
    float numer = 0.f;
    #pragma unroll
    for (int i = 0; i < 4; i++) {
        float gain = (float)((1 << vv[i]) - 1);
        numer += __fdividef(gain, __log2f(1.5f + FF[i]));   // pos = 0.5 + F
    }
    #pragma unroll
    for (int o = 16; o; o >>= 1) numer += __shfl_xor_sync(0xffffffffu, numer, o);
    if (lane == 0) sRed[w] = numer;
    __syncthreads();

    if (t == 0) {
        float x = 0.f;
        #pragma unroll
        for (int i = 0; i < 16; i++) x += sRed[i];
        // fixed-point row value: integer atomics commute -> deterministic sum.
        double val = (double)(x * sInv);
        u64 contrib = (u64)(val * 8796093022208.0 + 0.5);   // 2^43 scale
        u64 add = (contrib << 10) | 1ULL;
        u64 old = atomicAdd(&g_acc, add);
        if ((old & 1023ULL) == (u64)(BB - 1)) {             // 32nd (last) row
            u64 total = (old + add) >> 10;
            out[0] = (float)((double)total * (1.0 / (8796093022208.0 * BB)));
            g_acc = 0ULL;                                   // reset for replay
        }
    }
}

extern "C" void kernel_launch(void* const* d_in, const int* in_sizes, int n_in,
                              void* d_out, int out_size) {
    const float* yp = (const float*)d_in[0];
    const float* yt = (const float*)d_in[1];
    float* out = (float*)d_out;
    (void)in_sizes; (void)n_in; (void)out_size;

    dim3 g(4, BB);
    fused<<<g, 512>>>(yp, yt, out);
}